// round 9
// baseline (speedup 1.0000x reference)
#include <cuda_runtime.h>
#include <cstdint>

// Problem constants
#define BATCH   16
#define TLEN    4096
#define KW      15

// Tiling
#define TT      512     // time tile per CTA
#define TTH     16      // t positions per thread (8 packed adjacent pairs)
#define NTHREADS 256    // 8 warps; warp = 8 oc (lane&7) x 4 t-subtiles (lane>>3)
#define CHUNKI  4       // channels per staged chunk
#define NCHK    132     // 16-B chunks per channel image (pairs 0..263)
#define NRC     34      // chunks per interleave row (33 used + 1 pad col)
#define IMGU    (4*NRC*2)   // u64 per image  = 272
#define CHU     (2*IMGU)    // u64 per channel block (E then O) = 544

typedef unsigned long long u64;

// ---------------------------------------------------------------------------
// Intermediate activation buffers (static device globals; no runtime alloc)
// ---------------------------------------------------------------------------
__device__ float g_h1[(size_t)BATCH * 512 * TLEN];
__device__ float g_h2[(size_t)BATCH * 256 * TLEN];
__device__ float g_h3[(size_t)BATCH * 256 * TLEN];
__device__ float g_h4[(size_t)BATCH * 128 * TLEN];
__device__ float g_h5[(size_t)BATCH *  64 * TLEN];
__device__ float g_h6[(size_t)BATCH *  32 * TLEN];
__device__ float g_h7[(size_t)BATCH *  16 * TLEN];

// ---------------------------------------------------------------------------
// Packed f32x2 helpers (FFMA2 only reachable via PTX)
// ---------------------------------------------------------------------------
__device__ __forceinline__ u64 pack2(float lo, float hi) {
    u64 r; asm("mov.b64 %0,{%1,%2};" : "=l"(r) : "f"(lo), "f"(hi)); return r;
}
__device__ __forceinline__ void unpack2(u64 v, float& lo, float& hi) {
    asm("mov.b64 {%0,%1},%2;" : "=f"(lo), "=f"(hi) : "l"(v));
}
__device__ __forceinline__ u64 ffma2(u64 a, u64 b, u64 c) {
    u64 d; asm("fma.rn.f32x2 %0,%1,%2,%3;" : "=l"(d) : "l"(a), "l"(b), "l"(c));
    return d;
}
__device__ __forceinline__ void cpa16(uint32_t dst, const float* src, int sz) {
    asm volatile("cp.async.cg.shared.global [%0], [%1], 16, %2;\n"
                 :: "r"(dst), "l"(src), "r"(sz));
}
__device__ __forceinline__ void cpa_commit() { asm volatile("cp.async.commit_group;\n"); }
__device__ __forceinline__ void cpa_wait0()  { asm volatile("cp.async.wait_group 0;\n"); }

// ---------------------------------------------------------------------------
// Grouped conv1d K=15 SAME. X2[j] = x[t0-8+j] zero-padded. Pair images:
//   E[i] = (X2[2i],   X2[2i+1])   (serves ODD  taps k=2m-1: acc[a]+=w*E[q+m], m=1..7)
//   O[i] = (X2[2i+1], X2[2i+2])   (serves EVEN taps k=2m  : acc[a]+=w*O[q+m], m=0..7)
// Lane map: oc = lane&7, Q = warp*4 + (lane>>3) -> window LDS.128 is
// 4-address x 8-way-broadcast (64B, conflict-free, 1 phase); weight rows padded
// to CIN*16+2 u64 so the 8 oc rows hit banks {0,4,..,28} -> conflict-free.
// Images chunk-interleaved: chunk c (16B) at row c&3, col c>>2 -> thread's 8
// chunks per image sit at one row, consecutive cols => clean LDS.128.
// E staged by 16-B cp.async (edge chunks wholly in/out of range: exact zfill);
// O built in smem from E. Double-buffered chunks of CHUNKI channels.
// ---------------------------------------------------------------------------
template<int CIN, int C0, int COUT, bool ACT>
__global__ __launch_bounds__(NTHREADS, 3)
void gconv_kernel(const float* __restrict__ in0, long long bs0,
                  const float* __restrict__ in1, long long bs1,
                  const float* __restrict__ W,
                  const float* __restrict__ bias,
                  float* __restrict__ out, int G)
{
    extern __shared__ char smem_raw[];
    const int WROW2 = CIN * 16 + 2;                  // u64; +2 => oc rows 4 banks apart
    u64*   sw2  = (u64*)smem_raw;                    // COUT * WROW2
    u64*   simg = sw2 + COUT * WROW2;                // 2 bufs * CHUNKI * CHU
    float* sb   = (float*)(simg + 2 * CHUNKI * CHU);

    const int b   = blockIdx.z;
    const int g   = blockIdx.y;
    const int t0  = blockIdx.x * TT;
    const int tid = threadIdx.x;
    const int warp = tid >> 5, lane = tid & 31;
    const int oc = lane & 7;                         // 8 oc per warp -> broadcast windows
    const int Q  = warp * 4 + (lane >> 3);           // 0..31, t base = Q*16

    // ---- stage SOA packed weights: slot s<8 -> w[2s] (even k); s=8..14 -> w[2(s-8)+1]
    {
        const float* wsrc = W + (long long)g * COUT * CIN * KW;
        for (int i = tid; i < COUT * CIN * 16; i += NTHREADS) {
            int o_ = i / (CIN * 16);
            int r  = i - o_ * (CIN * 16);
            int ci = r >> 4, s = r & 15;
            float w = 0.0f;
            if (s < 8)       w = wsrc[(o_ * CIN + ci) * KW + 2 * s];
            else if (s < 15) w = wsrc[(o_ * CIN + ci) * KW + 2 * (s - 8) + 1];
            sw2[o_ * WROW2 + r] = pack2(w, w);
        }
        if (tid < COUT) sb[tid] = bias[g * COUT + tid];
    }

    auto srcbase = [&](int ci) -> const float* {
        if (C0 == CIN || ci < C0)
            return in0 + (long long)b * bs0 + (long long)(g * C0 + ci) * TLEN;
        return in1 + (long long)b * bs1 + (long long)(g * (CIN - C0) + (ci - C0)) * TLEN;
    };

    // stage E images of channels [c0, c0+CHUNKI) into buffer buf via 16-B cp.async
    auto stageE = [&](int c0, int buf) {
        u64* base = simg + buf * (CHUNKI * CHU);
        uint32_t aB = (uint32_t)__cvta_generic_to_shared(base);
        for (int idx = tid; idx < CHUNKI * NCHK; idx += NTHREADS) {
            int cl = idx / NCHK, c = idx - cl * NCHK;
            const float* src = srcbase(c0 + cl);
            int f  = t0 - 8 + 4 * c;                       // multiple of 4
            int sz = ((unsigned)f < (unsigned)(TLEN - 3)) ? 16 : 0;
            int fc = f < 0 ? 0 : (f > TLEN - 4 ? TLEN - 4 : f);
            uint32_t dst = aB + (uint32_t)(cl * CHU * 8)
                              + (uint32_t)((((c & 3) * NRC) + (c >> 2)) * 16);
            cpa16(dst, src + fc, sz);
        }
    };

    // build O images from E (O chunk c floats = X2[4c+1..4c+4])
    auto buildO = [&](int buf) {
        u64* base = simg + buf * (CHUNKI * CHU);
        for (int idx = tid; idx < CHUNKI * NCHK; idx += NTHREADS) {
            int cl = idx / NCHK, c = idx - cl * NCHK;
            float* E = (float*)(base + cl * CHU);
            float* O = E + IMGU * 2;                       // floats
            int p0 = (((c & 3) * NRC) + (c >> 2)) * 4;
            int c1 = c + 1;
            int p1 = ((((c1) & 3) * NRC) + (c1 >> 2)) * 4; // c=131 -> pad col 33
            float4 v = *(float4*)(E + p0);
            float nxt = E[p1];
            *(float4*)(O + p0) = make_float4(v.y, v.z, v.w, nxt);
        }
    };

    u64 acc[8];
#pragma unroll
    for (int j = 0; j < 8; j++) acc[j] = 0ull;

    const u64* wrow = sw2 + oc * WROW2;

    // prologue: chunk 0
    stageE(0, 0); cpa_commit(); cpa_wait0();
    __syncthreads();                 // E(0) + weights visible
    buildO(0);
    __syncthreads();

    const int NCH = CIN / CHUNKI;
#pragma unroll 1
    for (int c = 0; c < NCH; c++) {
        const int buf = c & 1;
        if (c + 1 < NCH) stageE((c + 1) * CHUNKI, buf ^ 1);
        cpa_commit();

        u64* bufb = simg + buf * (CHUNKI * CHU);
#pragma unroll 1
        for (int cl = 0; cl < CHUNKI; cl++) {
            const u64* Ei = bufb + cl * CHU + Q * 2;
            const u64* Oi = Ei + IMGU;
            const u64* wp = wrow + (c * CHUNKI + cl) * 16;

            // ---- even-k pass (O image), m = 0..7 ----
            {
                u64 wv[8];
#pragma unroll
                for (int j = 0; j < 4; j++) {
                    ulonglong2 v = ((const ulonglong2*)wp)[j];
                    wv[2*j] = v.x; wv[2*j+1] = v.y;
                }
                u64 o[16];
#pragma unroll
                for (int s = 0; s < 8; s++) {
                    ulonglong2 v = *(const ulonglong2*)(Oi + (s & 3) * (2 * NRC) + (s >> 2) * 2);
                    o[2*s] = v.x; o[2*s+1] = v.y;
                }
#pragma unroll
                for (int m = 0; m < 8; m++) {
#pragma unroll
                    for (int a = 0; a < 8; a++) acc[a] = ffma2(o[a + m], wv[m], acc[a]);
                }
            }
            // ---- odd-k pass (E image), m = 1..7 ----
            {
                u64 wv[8];
#pragma unroll
                for (int j = 0; j < 4; j++) {
                    ulonglong2 v = ((const ulonglong2*)wp)[4 + j];
                    wv[2*j] = v.x; wv[2*j+1] = v.y;
                }
                u64 e[16];
#pragma unroll
                for (int s = 0; s < 8; s++) {
                    ulonglong2 v = *(const ulonglong2*)(Ei + (s & 3) * (2 * NRC) + (s >> 2) * 2);
                    e[2*s] = v.x; e[2*s+1] = v.y;
                }
#pragma unroll
                for (int m = 1; m < 8; m++) {
#pragma unroll
                    for (int a = 0; a < 8; a++) acc[a] = ffma2(e[a + m], wv[m - 1], acc[a]);
                }
            }
        }

        if (c + 1 < NCH) {
            cpa_wait0();
            __syncthreads();         // E(c+1) landed; compute(c) done
            buildO(buf ^ 1);
            __syncthreads();         // O(c+1) visible
        }
    }

    // ---- epilogue: bias + leaky relu, vectorized store ----
    const float bv = sb[oc];
    float res[TTH];
#pragma unroll
    for (int j = 0; j < 8; j++) {
        float lo, hi;
        unpack2(acc[j], lo, hi);
        lo += bv; hi += bv;
        if (ACT) { lo = lo > 0.0f ? lo : 0.01f * lo; hi = hi > 0.0f ? hi : 0.01f * hi; }
        res[2*j] = lo; res[2*j+1] = hi;
    }
    float* dst = out + (((long long)b * G + g) * COUT + oc) * TLEN + t0 + Q * TTH;
#pragma unroll
    for (int j = 0; j < 4; j++)
        ((float4*)dst)[j] = make_float4(res[4*j], res[4*j+1], res[4*j+2], res[4*j+3]);
}

// ---------------------------------------------------------------------------
// Root: 1x1 conv over 16 channels -> 1 channel (no activation)
// ---------------------------------------------------------------------------
__global__ void root_kernel(const float* __restrict__ h,
                            const float* __restrict__ w,
                            const float* __restrict__ bias,
                            float* __restrict__ out)
{
    int idx = blockIdx.x * blockDim.x + threadIdx.x;
    if (idx >= BATCH * TLEN) return;
    int b = idx / TLEN;
    int t = idx - b * TLEN;
    const float* hp = h + (long long)b * 16 * TLEN + t;
    float s = bias[0];
#pragma unroll
    for (int c = 0; c < 16; c++)
        s = fmaf(__ldg(&w[c]), hp[(long long)c * TLEN], s);
    out[idx] = s;
}

// ---------------------------------------------------------------------------
// Launch
// ---------------------------------------------------------------------------
static inline int smem_bytes(int cin, int cout) {
    return cout * (cin * 16 + 2) * 8      // SOA packed weights (padded rows)
         + 2 * CHUNKI * CHU * 8           // double-buffered E+O chunk images
         + cout * 4;                      // bias
}

extern "C" void kernel_launch(void* const* d_in, const int* in_sizes, int n_in,
                              void* d_out, int out_size)
{
    const float* x      = (const float*)d_in[0];
    const float* W_leaf = (const float*)d_in[1];
    const float* b_leaf = (const float*)d_in[2];
    const float* W_int0 = (const float*)d_in[3];
    const float* b_int0 = (const float*)d_in[4];
    const float* W_br   = (const float*)d_in[5];
    const float* b_br   = (const float*)d_in[6];
    const float* W_int1 = (const float*)d_in[7];
    const float* b_int1 = (const float*)d_in[8];
    const float* W_int2 = (const float*)d_in[9];
    const float* b_int2 = (const float*)d_in[10];
    const float* W_int3 = (const float*)d_in[11];
    const float* b_int3 = (const float*)d_in[12];
    const float* W_int4 = (const float*)d_in[13];
    const float* b_int4 = (const float*)d_in[14];
    const float* W_root = (const float*)d_in[15];
    const float* b_root = (const float*)d_in[16];
    float* out = (float*)d_out;

    float *h1, *h2, *h3, *h4, *h5, *h6, *h7;
    cudaGetSymbolAddress((void**)&h1, g_h1);
    cudaGetSymbolAddress((void**)&h2, g_h2);
    cudaGetSymbolAddress((void**)&h3, g_h3);
    cudaGetSymbolAddress((void**)&h4, g_h4);
    cudaGetSymbolAddress((void**)&h5, g_h5);
    cudaGetSymbolAddress((void**)&h6, g_h6);
    cudaGetSymbolAddress((void**)&h7, g_h7);

    const int TB = TLEN / TT;   // 8 tiles along T
    const long long BSX = (long long)1536 * TLEN;

    const int SM20 = smem_bytes(20, 8);   // ~55 KB -> 3 CTAs/SM
    const int SM16 = smem_bytes(16, 8);   // ~50 KB -> 3 CTAs/SM

    cudaFuncSetAttribute(gconv_kernel<20, 20, 8, true>,
                         cudaFuncAttributeMaxDynamicSharedMemorySize, SM20);
    cudaFuncSetAttribute(gconv_kernel<16, 16, 8, true>,
                         cudaFuncAttributeMaxDynamicSharedMemorySize, SM16);
    cudaFuncSetAttribute(gconv_kernel<16, 8, 8, true>,
                         cudaFuncAttributeMaxDynamicSharedMemorySize, SM16);

    // 1. leaf: 64 groups, 20 in/group, 8 out/group (5 chunks of 4)
    gconv_kernel<20, 20, 8, true><<<dim3(TB, 64, BATCH), NTHREADS, SM20>>>(
        x, BSX, nullptr, 0, W_leaf, b_leaf, h1, 64);

    // 2. int0: 32 groups, 16 in/group (from 512 ch)
    gconv_kernel<16, 16, 8, true><<<dim3(TB, 32, BATCH), NTHREADS, SM16>>>(
        h1, (long long)512 * TLEN, nullptr, 0, W_int0, b_int0, h2, 32);

    // 3. br: 32 groups, in/group = 8 (h2) + 8 (syn = x channels 1280..1535)
    gconv_kernel<16, 8, 8, true><<<dim3(TB, 32, BATCH), NTHREADS, SM16>>>(
        h2, (long long)256 * TLEN,
        x + (long long)1280 * TLEN, BSX,
        W_br, b_br, h3, 32);

    // 4. int1: 16 groups (256 -> 128)
    gconv_kernel<16, 16, 8, true><<<dim3(TB, 16, BATCH), NTHREADS, SM16>>>(
        h3, (long long)256 * TLEN, nullptr, 0, W_int1, b_int1, h4, 16);

    // 5. int2: 8 groups (128 -> 64)
    gconv_kernel<16, 16, 8, true><<<dim3(TB, 8, BATCH), NTHREADS, SM16>>>(
        h4, (long long)128 * TLEN, nullptr, 0, W_int2, b_int2, h5, 8);

    // 6. int3: 4 groups (64 -> 32)
    gconv_kernel<16, 16, 8, true><<<dim3(TB, 4, BATCH), NTHREADS, SM16>>>(
        h5, (long long)64 * TLEN, nullptr, 0, W_int3, b_int3, h6, 4);

    // 7. int4: 2 groups (32 -> 16)
    gconv_kernel<16, 16, 8, true><<<dim3(TB, 2, BATCH), NTHREADS, SM16>>>(
        h6, (long long)32 * TLEN, nullptr, 0, W_int4, b_int4, h7, 2);

    // 8. root: 1x1 conv 16 -> 1
    root_kernel<<<(BATCH * TLEN + 255) / 256, 256>>>(h7, W_root, b_root, out);
}